// round 2
// baseline (speedup 1.0000x reference)
#include <cuda_runtime.h>

#define BB 4
#define CC 64
#define WDIM 64
#define NN 4096
#define DQ 10
#define QW 4
#define WARPS 8
#define BLOCK_Q 32
#define KT 64
#define NTASK (BB*(NN/BLOCK_Q))   // 512
#define GRID_ATTN 296

// Scratch (device globals; no allocation allowed)
__device__ __align__(16) float g_QP[BB][NN][12];   // q' (8 dims used)
__device__ __align__(16) float g_KP[BB][DQ][NN];   // k' channel-major (8,9 = centered col,row)
__device__ __align__(16) float g_VT[BB][NN][CC];   // v [key][channel]
__device__ int g_maxk[BB][8];                       // bit patterns of max|k_d| (>=0)

__device__ __forceinline__ void fma2(unsigned long long& d,
                                     unsigned long long a,
                                     unsigned long long b) {
    asm("fma.rn.f32x2 %0, %1, %2, %0;" : "+l"(d) : "l"(a), "l"(b));
}
__device__ __forceinline__ float2 unpack2(unsigned long long v) {
    float2 r;
    asm("mov.b64 {%0,%1}, %2;" : "=f"(r.x), "=f"(r.y) : "l"(v));
    return r;
}
__device__ __forceinline__ float ex2(float x) {
    float r;
    asm("ex2.approx.f32 %0, %1;" : "=f"(r) : "f"(x));
    return r;
}

// ---------------------------------------------------------------------------
// Prep: 1x1 convs -> q', k', v + per-channel max|k| (for softmax bound)
// ---------------------------------------------------------------------------
__global__ __launch_bounds__(64) void prep_kernel(
    const float* __restrict__ x,
    const float* __restrict__ Wq, const float* __restrict__ bq,
    const float* __restrict__ Wk, const float* __restrict__ bk,
    const float* __restrict__ Wv, const float* __restrict__ bv)
{
    __shared__ float xs[CC][64];
    __shared__ float wv_s[CC][CC];
    __shared__ float wq_s[8][CC];
    __shared__ float wk_s[8][CC];
    __shared__ float bv_s[CC];
    __shared__ float bq_s[8], bk_s[8];

    int b  = blockIdx.x / (NN/64);
    int n0 = (blockIdx.x % (NN/64)) * 64;
    int t  = threadIdx.x;

    #pragma unroll 8
    for (int c = 0; c < CC; c++)
        xs[c][t] = x[(b*CC + c)*NN + n0 + t];

    for (int i = t; i < CC*CC; i += 64) wv_s[i/CC][i%CC] = Wv[i];
    for (int i = t; i < 8*CC;  i += 64) { wq_s[i/CC][i%CC] = Wq[i]; wk_s[i/CC][i%CC] = Wk[i]; }
    if (t < CC) bv_s[t] = bv[t];
    if (t < 8)  { bq_s[t] = bq[t]; bk_s[t] = bk[t]; }
    __syncthreads();

    float accv[CC];
    float accq[8], acck[8];
    #pragma unroll
    for (int e = 0; e < CC; e++) accv[e] = 0.f;
    #pragma unroll
    for (int d = 0; d < 8; d++) { accq[d] = 0.f; acck[d] = 0.f; }

    for (int c = 0; c < CC; c++) {
        float xc = xs[c][t];
        #pragma unroll
        for (int e = 0; e < CC; e++) accv[e] = fmaf(wv_s[e][c], xc, accv[e]);
        #pragma unroll
        for (int d = 0; d < 8; d++) {
            accq[d] = fmaf(wq_s[d][c], xc, accq[d]);
            acck[d] = fmaf(wk_s[d][c], xc, acck[d]);
        }
    }

    int n = n0 + t;
    #pragma unroll
    for (int d = 0; d < 8; d++) g_QP[b][n][d] = accq[d] + bq_s[d];

    #pragma unroll
    for (int d = 0; d < 8; d++) {
        float kv = acck[d] + bk_s[d];
        g_KP[b][d][n] = kv;
        float a = fabsf(kv);
        #pragma unroll
        for (int o = 16; o > 0; o >>= 1)
            a = fmaxf(a, __shfl_xor_sync(0xffffffffu, a, o));
        if ((t & 31) == 0) atomicMax(&g_maxk[b][d], __float_as_int(a));
    }
    // centered rel-pos key channels (softmax-invariant shift)
    g_KP[b][8][n] = (float)(n % WDIM) - 31.5f;
    g_KP[b][9][n] = (float)(n / WDIM) - 31.5f;

    #pragma unroll
    for (int e = 0; e < CC; e++) g_VT[b][n][e] = accv[e] + bv_s[e];
}

// ---------------------------------------------------------------------------
// Flash attention, persistent grid, f32x2-packed PV, bound-based softmax.
// ---------------------------------------------------------------------------
__global__ __launch_bounds__(256, 2) void attn_kernel(float* __restrict__ out)
{
    __shared__ __align__(16) float kp_s[DQ][KT];          // 2.5 KB
    __shared__ __align__(16) float v_s[KT][2*CC];         // 32 KB, splatted {v,v,v',v'}
    __shared__ __align__(16) float p_s[WARPS][KT][4];     // 4 KB, [key][query]

    const int t = threadIdx.x;
    const int w = t >> 5;
    const int l = t & 31;
    const float L2E = 1.44269504088896f;

    for (int task = blockIdx.x; task < NTASK; task += gridDim.x) {
        const int b  = task >> 7;
        const int n0 = (task & 127) * BLOCK_Q;

        // per-warp query registers (channels 8,9 duplicate 0,1 -> reuse)
        float qr[QW][8];
        float bnd[QW], Sm[QW];
        unsigned long long acc00 = 0, acc01 = 0, acc10 = 0, acc11 = 0;

        float mk[8];
        #pragma unroll
        for (int d = 0; d < 8; d++) mk[d] = __int_as_float(g_maxk[b][d]);

        #pragma unroll
        for (int q = 0; q < QW; q++) {
            const float* qp = g_QP[b][n0 + w*QW + q];
            float bb = 0.f;
            #pragma unroll
            for (int d = 0; d < 8; d++) {
                qr[q][d] = qp[d];
                bb = fmaf(fabsf(qr[q][d]), mk[d], bb);
            }
            bb += 31.5f * (fabsf(qr[q][0]) + fabsf(qr[q][1]));
            bnd[q] = bb * L2E;      // prescaled: p = ex2(s*L2E - bnd)
            Sm[q] = 0.f;
        }

        for (int kt = 0; kt < NN/KT; kt++) {
            const int m0 = kt * KT;
            __syncthreads();
            // stage k' tile: 10 x 64 floats = 160 float4
            if (t < 160) {
                int d = t >> 4, j4 = t & 15;
                *(float4*)&kp_s[d][j4*4] = *(const float4*)&g_KP[b][d][m0 + j4*4];
            }
            // stage v tile splatted: v_s[key][2c..2c+1] = {v[c], v[c]}
            #pragma unroll
            for (int i = 0; i < 4; i++) {
                int idx = t + 256*i;
                int key = idx >> 4, c4 = idx & 15;
                float4 vv = *(const float4*)&g_VT[b][m0 + key][c4*4];
                float* dst = &v_s[key][c4*8];
                *(float4*)(dst)     = make_float4(vv.x, vv.x, vv.y, vv.y);
                *(float4*)(dst + 4) = make_float4(vv.z, vv.z, vv.w, vv.w);
            }
            __syncthreads();

            // scores for keys 2l, 2l+1 over 4 queries (scalar FFMA)
            float s0[QW], s1[QW];
            #pragma unroll
            for (int q = 0; q < QW; q++) { s0[q] = 0.f; s1[q] = 0.f; }
            #pragma unroll
            for (int d = 0; d < 8; d++) {
                float2 kk = *(const float2*)&kp_s[d][2*l];
                #pragma unroll
                for (int q = 0; q < QW; q++) {
                    s0[q] = fmaf(qr[q][d], kk.x, s0[q]);
                    s1[q] = fmaf(qr[q][d], kk.y, s1[q]);
                }
            }
            {   // rel-pos channels reuse q0, q1
                float2 kc = *(const float2*)&kp_s[8][2*l];
                float2 kr = *(const float2*)&kp_s[9][2*l];
                #pragma unroll
                for (int q = 0; q < QW; q++) {
                    s0[q] = fmaf(qr[q][0], kc.x, s0[q]);
                    s1[q] = fmaf(qr[q][0], kc.y, s1[q]);
                    s0[q] = fmaf(qr[q][1], kr.x, s0[q]);
                    s1[q] = fmaf(qr[q][1], kr.y, s1[q]);
                }
            }

            // p = ex2(s*L2E - bnd); store key-major for packed PV
            float pA[QW], pB[QW];
            #pragma unroll
            for (int q = 0; q < QW; q++) {
                pA[q] = ex2(fmaf(s0[q], L2E, -bnd[q]));
                pB[q] = ex2(fmaf(s1[q], L2E, -bnd[q]));
                Sm[q] += pA[q] + pB[q];
            }
            *(float4*)p_s[w][2*l]     = make_float4(pA[0], pA[1], pA[2], pA[3]);
            *(float4*)p_s[w][2*l + 1] = make_float4(pB[0], pB[1], pB[2], pB[3]);
            __syncwarp();

            // PV: packed f32x2, lane owns channels (2l, 2l+1), query pairs packed
            #pragma unroll 8
            for (int j = 0; j < KT; j++) {
                ulonglong2 pp = *(const ulonglong2*)p_s[w][j];          // {p_q0,p_q1},{p_q2,p_q3}
                ulonglong2 vv = *(const ulonglong2*)&v_s[j][4*l];       // {v0,v0},{v1,v1}
                fma2(acc00, pp.x, vv.x);
                fma2(acc01, pp.x, vv.y);
                fma2(acc10, pp.y, vv.x);
                fma2(acc11, pp.y, vv.y);
            }
        }

        // epilogue: reduce Sm across lanes, normalize, store
        float inv[QW];
        #pragma unroll
        for (int q = 0; q < QW; q++) {
            float s = Sm[q];
            #pragma unroll
            for (int o = 16; o > 0; o >>= 1)
                s += __shfl_xor_sync(0xffffffffu, s, o);
            inv[q] = 1.0f / s;
        }
        float2 a00 = unpack2(acc00);   // (q0, q1) @ c0
        float2 a01 = unpack2(acc01);   // (q0, q1) @ c1
        float2 a10 = unpack2(acc10);   // (q2, q3) @ c0
        float2 a11 = unpack2(acc11);   // (q2, q3) @ c1
        const int nq = n0 + w*QW;
        float* o0 = out + (b*CC + 2*l    )*NN + nq;
        float* o1 = out + (b*CC + 2*l + 1)*NN + nq;
        o0[0] = a00.x * inv[0];  o0[1] = a00.y * inv[1];
        o0[2] = a10.x * inv[2];  o0[3] = a10.y * inv[3];
        o1[0] = a01.x * inv[0];  o1[1] = a01.y * inv[1];
        o1[2] = a11.x * inv[2];  o1[3] = a11.y * inv[3];
    }
}

extern "C" void kernel_launch(void* const* d_in, const int* in_sizes, int n_in,
                              void* d_out, int out_size)
{
    const float* x  = (const float*)d_in[0];
    const float* Wq = (const float*)d_in[1];
    const float* bq = (const float*)d_in[2];
    const float* Wk = (const float*)d_in[3];
    const float* bk = (const float*)d_in[4];
    const float* Wv = (const float*)d_in[5];
    const float* bv = (const float*)d_in[6];
    float* out = (float*)d_out;

    prep_kernel<<<BB*(NN/64), 64>>>(x, Wq, bq, Wk, bk, Wv, bv);
    attn_kernel<<<GRID_ATTN, 256>>>(out);
}

// round 4
// speedup vs baseline: 7.4180x; 7.4180x over previous
#include <cuda_runtime.h>
#include <cuda_bf16.h>
#include <stdint.h>

#define BB 4
#define CC 64
#define WDIM 64
#define NN 4096
#define MQ 128
#define KTILE 64
#define NTILES (NN/KTILE)
#define L2E 1.44269504088896f

#define QSTRIDE 80
#define KSTRIDE 80
#define VSTRIDE 144
#define SM_Q   0
#define SM_K   10240
#define KBUF   5120
#define SM_VH  20480
#define VBUF   9216
#define SM_VL  38912
#define SMEM_TOTAL 57344

// ---- global scratch ----
__device__ float g_QPf[BB*NN*8];
__device__ int   g_maxk[BB][8];
__device__ __align__(16) __nv_bfloat16 g_Q16[BB*NN*32];
__device__ __align__(16) __nv_bfloat16 g_K16[BB*NN*32];
__device__ __align__(16) __nv_bfloat16 g_Vh[BB*NN*CC];
__device__ __align__(16) __nv_bfloat16 g_Vl[BB*NN*CC];

// ---- helpers ----
__device__ __forceinline__ uint32_t s2u(const void* p) {
    uint32_t a;
    asm("{ .reg .u64 t; cvta.to.shared.u64 t, %1; cvt.u32.u64 %0, t; }" : "=r"(a) : "l"(p));
    return a;
}
__device__ __forceinline__ float ex2f(float x) {
    float r; asm("ex2.approx.f32 %0, %1;" : "=f"(r) : "f"(x)); return r;
}
// packs: lower 16 = lo, upper 16 = hi
__device__ __forceinline__ uint32_t cvt2bf(float hi, float lo) {
    uint32_t r; asm("cvt.rn.bf16x2.f32 %0, %1, %2;" : "=r"(r) : "f"(hi), "f"(lo)); return r;
}
__device__ __forceinline__ void cpa16(uint32_t dst, const void* src) {
    asm volatile("cp.async.cg.shared.global [%0], [%1], 16;" :: "r"(dst), "l"(src));
}
__device__ __forceinline__ void ldsm4(uint32_t* r, uint32_t a) {
    asm volatile("ldmatrix.sync.aligned.m8n8.x4.shared.b16 {%0,%1,%2,%3}, [%4];"
        : "=r"(r[0]), "=r"(r[1]), "=r"(r[2]), "=r"(r[3]) : "r"(a));
}
__device__ __forceinline__ void ldsm4t(uint32_t* r, uint32_t a) {
    asm volatile("ldmatrix.sync.aligned.m8n8.x4.trans.shared.b16 {%0,%1,%2,%3}, [%4];"
        : "=r"(r[0]), "=r"(r[1]), "=r"(r[2]), "=r"(r[3]) : "r"(a));
}
__device__ __forceinline__ void mma16816(float* d, const uint32_t* a, const uint32_t* b) {
    asm volatile(
        "mma.sync.aligned.m16n8k16.row.col.f32.bf16.bf16.f32 "
        "{%0,%1,%2,%3}, {%4,%5,%6,%7}, {%8,%9}, {%0,%1,%2,%3};"
        : "+f"(d[0]), "+f"(d[1]), "+f"(d[2]), "+f"(d[3])
        : "r"(a[0]), "r"(a[1]), "r"(a[2]), "r"(a[3]), "r"(b[0]), "r"(b[1]));
}

// ---------------------------------------------------------------------------
// Prep: 1x1 convs -> bf16 hi/lo operand tensors + fp32 q + max|k|
// ---------------------------------------------------------------------------
__global__ __launch_bounds__(64) void prep_kernel(
    const float* __restrict__ x,
    const float* __restrict__ Wq, const float* __restrict__ bq,
    const float* __restrict__ Wk, const float* __restrict__ bk,
    const float* __restrict__ Wv, const float* __restrict__ bv)
{
    __shared__ float xs[CC][64];
    __shared__ float wv_s[CC][CC];
    __shared__ float wq_s[8][CC];
    __shared__ float wk_s[8][CC];
    __shared__ float bv_s[CC];
    __shared__ float bq_s[8], bk_s[8];

    int b  = blockIdx.x / (NN/64);
    int n0 = (blockIdx.x % (NN/64)) * 64;
    int t  = threadIdx.x;

    #pragma unroll 8
    for (int c = 0; c < CC; c++)
        xs[c][t] = x[(b*CC + c)*NN + n0 + t];
    for (int i = t; i < CC*CC; i += 64) wv_s[i/CC][i%CC] = Wv[i];
    for (int i = t; i < 8*CC;  i += 64) { wq_s[i/CC][i%CC] = Wq[i]; wk_s[i/CC][i%CC] = Wk[i]; }
    if (t < CC) bv_s[t] = bv[t];
    if (t < 8)  { bq_s[t] = bq[t]; bk_s[t] = bk[t]; }
    __syncthreads();

    float accv[CC], accq[8], acck[8];
    #pragma unroll
    for (int e = 0; e < CC; e++) accv[e] = 0.f;
    #pragma unroll
    for (int d = 0; d < 8; d++) { accq[d] = 0.f; acck[d] = 0.f; }

    for (int c = 0; c < CC; c++) {
        float xc = xs[c][t];
        #pragma unroll
        for (int e = 0; e < CC; e++) accv[e] = fmaf(wv_s[e][c], xc, accv[e]);
        #pragma unroll
        for (int d = 0; d < 8; d++) {
            accq[d] = fmaf(wq_s[d][c], xc, accq[d]);
            acck[d] = fmaf(wk_s[d][c], xc, acck[d]);
        }
    }

    int n = n0 + t;
    float qv[8], kv[8];
    #pragma unroll
    for (int d = 0; d < 8; d++) { qv[d] = accq[d] + bq_s[d]; kv[d] = acck[d] + bk_s[d]; }

    #pragma unroll
    for (int d = 0; d < 8; d++) g_QPf[(size_t)(b*NN + n)*8 + d] = qv[d];

    #pragma unroll
    for (int d = 0; d < 8; d++) {
        float a = fabsf(kv[d]);
        #pragma unroll
        for (int o = 16; o > 0; o >>= 1)
            a = fmaxf(a, __shfl_xor_sync(0xffffffffu, a, o));
        if ((t & 31) == 0) atomicMax(&g_maxk[b][d], __float_as_int(a));
    }

    // ---- Q row: 16 hi dims (8-15: dup q0,q1 + zeros), 16 lo dims ----
    {
        uint32_t u[16];
        float lo[8];
        #pragma unroll
        for (int i = 0; i < 4; i++) {
            uint32_t h = cvt2bf(qv[2*i+1], qv[2*i]);
            u[i] = h;
            float h0 = __uint_as_float(h << 16);
            float h1 = __uint_as_float(h & 0xFFFF0000u);
            lo[2*i] = qv[2*i] - h0; lo[2*i+1] = qv[2*i+1] - h1;
        }
        u[4] = u[0];                 // dims 8,9 = dup(q0,q1) hi
        u[5] = 0; u[6] = 0; u[7] = 0;
        #pragma unroll
        for (int i = 0; i < 4; i++) u[8+i] = cvt2bf(lo[2*i+1], lo[2*i]);
        u[12] = u[8];                // dims 24,25 = dup lo(q0,q1)
        u[13] = 0; u[14] = 0; u[15] = 0;
        uint4* dst = (uint4*)&g_Q16[(size_t)(b*NN + n)*32];
        dst[0] = make_uint4(u[0],u[1],u[2],u[3]);
        dst[1] = make_uint4(u[4],u[5],u[6],u[7]);
        dst[2] = make_uint4(u[8],u[9],u[10],u[11]);
        dst[3] = make_uint4(u[12],u[13],u[14],u[15]);
    }
    // ---- K row ----
    {
        uint32_t u[16];
        float lo[8];
        #pragma unroll
        for (int i = 0; i < 4; i++) {
            uint32_t h = cvt2bf(kv[2*i+1], kv[2*i]);
            u[i] = h;
            float h0 = __uint_as_float(h << 16);
            float h1 = __uint_as_float(h & 0xFFFF0000u);
            lo[2*i] = kv[2*i] - h0; lo[2*i+1] = kv[2*i+1] - h1;
        }
        float colc = (float)(n % WDIM) - 31.5f;   // exact in bf16
        float rowc = (float)(n / WDIM) - 31.5f;
        u[4] = cvt2bf(rowc, colc);    // dims 8,9
        u[5] = 0; u[6] = 0; u[7] = 0;
        #pragma unroll
        for (int i = 0; i < 4; i++) u[8+i] = cvt2bf(lo[2*i+1], lo[2*i]);
        u[12] = 0;                    // rel-pos lo = 0 (exact)
        u[13] = 0; u[14] = 0; u[15] = 0;
        uint4* dst = (uint4*)&g_K16[(size_t)(b*NN + n)*32];
        dst[0] = make_uint4(u[0],u[1],u[2],u[3]);
        dst[1] = make_uint4(u[4],u[5],u[6],u[7]);
        dst[2] = make_uint4(u[8],u[9],u[10],u[11]);
        dst[3] = make_uint4(u[12],u[13],u[14],u[15]);
    }
    // ---- V hi/lo, [key][ch] layout ----
    #pragma unroll
    for (int e = 0; e < CC; e++) {
        float v = accv[e] + bv_s[e];
        __nv_bfloat16 vh = __float2bfloat16(v);
        float vl = v - __bfloat162float(vh);
        g_Vh[(size_t)(b*NN + n)*CC + e] = vh;
        g_Vl[(size_t)(b*NN + n)*CC + e] = __float2bfloat16(vl);
    }
}

// ---------------------------------------------------------------------------
// mma.sync flash attention: 128 CTAs x 256 threads, 128 queries/CTA,
// 16 query rows per warp, bound-based softmax (no row max, no rescale).
// ---------------------------------------------------------------------------
#define STAGE(tile, bbuf) do {                                              \
    int m0s = (tile)*KTILE;                                                 \
    { int row = t >> 2, seg = t & 3;                                        \
      cpa16(sb + SM_K + (bbuf)*KBUF + row*KSTRIDE + seg*16,                 \
            &g_K16[(size_t)(b*NN + m0s + row)*32 + seg*8]); }               \
    _Pragma("unroll")                                                       \
    for (int j5 = 0; j5 < 2; j5++) {                                        \
        int id = t + 256*j5; int row = id >> 3, seg = id & 7;               \
        cpa16(sb + SM_VH + (bbuf)*VBUF + row*VSTRIDE + seg*16,              \
              &g_Vh[(size_t)(b*NN + m0s + row)*CC + seg*8]);                \
        cpa16(sb + SM_VL + (bbuf)*VBUF + row*VSTRIDE + seg*16,              \
              &g_Vl[(size_t)(b*NN + m0s + row)*CC + seg*8]);                \
    }                                                                       \
} while (0)

__global__ __launch_bounds__(256, 1) void attn_kernel(float* __restrict__ out)
{
    extern __shared__ char smem[];
    const uint32_t sb = s2u(smem);
    const int t = threadIdx.x;
    const int w = t >> 5;
    const int l = t & 31;
    const int b  = blockIdx.x >> 5;
    const int n0 = (blockIdx.x & 31) * MQ;
    const int qr0 = w * 16;

    // stage Q (plain loads)
    #pragma unroll
    for (int j = 0; j < 2; j++) {
        int id = t + 256*j;
        int row = id >> 2, seg = id & 3;
        uint4 v = *(const uint4*)&g_Q16[(size_t)(b*NN + n0 + row)*32 + seg*8];
        *(uint4*)(smem + SM_Q + row*QSTRIDE + seg*16) = v;
    }

    // prefetch tile 0
    STAGE(0, 0);
    asm volatile("cp.async.commit_group;" ::: "memory");

    // softmax bounds for this lane's two query rows (qr+l/4, +8)
    float bndA, bndB;
    {
        int rA = n0 + qr0 + (l >> 2);
        const float* qa = &g_QPf[(size_t)(b*NN + rA)*8];
        const float* qb = qa + 8*8;
        float ba = 0.f, bb2 = 0.f;
        #pragma unroll
        for (int d = 0; d < 8; d++) {
            float mk = __int_as_float(g_maxk[b][d]);
            float qda = fabsf(qa[d]), qdb = fabsf(qb[d]);
            ba  = fmaf(qda, mk, ba);
            bb2 = fmaf(qdb, mk, bb2);
            if (d < 2) { ba += 31.5f*qda; bb2 += 31.5f*qdb; }
        }
        bndA = ba * L2E; bndB = bb2 * L2E;
    }

    __syncthreads();   // Q staged

    uint32_t qh[4], ql[4];
    {
        uint32_t qa = sb + SM_Q + (qr0 + (l & 7) + ((l >> 3) & 1)*8)*QSTRIDE + (l >> 4)*16;
        ldsm4(qh, qa);
        ldsm4(ql, qa + 32);
    }

    float O[8][4];
    #pragma unroll
    for (int j = 0; j < 8; j++) { O[j][0]=0.f; O[j][1]=0.f; O[j][2]=0.f; O[j][3]=0.f; }
    float sumA = 0.f, sumB = 0.f;

    for (int tt = 0; tt < NTILES; tt++) {
        const int bbuf = tt & 1;
        if (tt + 1 < NTILES) STAGE(tt + 1, (tt + 1) & 1);
        asm volatile("cp.async.commit_group;" ::: "memory");
        asm volatile("cp.async.wait_group 1;" ::: "memory");
        __syncthreads();

        // ---- scores: S = qh*kh + qh*kl + ql*kh ----
        const uint32_t kbase = sb + SM_K + bbuf*KBUF;
        float S[8][4];
        #pragma unroll
        for (int p2 = 0; p2 < 4; p2++) {
            uint32_t ka = kbase + (p2*16 + (l & 7) + (l >> 4)*8)*KSTRIDE + ((l >> 3) & 1)*16;
            uint32_t kh[4], kl[4];
            ldsm4(kh, ka);
            ldsm4(kl, ka + 32);
            float* s0 = S[2*p2]; float* s1 = S[2*p2+1];
            s0[0]=0.f; s0[1]=0.f; s0[2]=0.f; s0[3]=0.f;
            s1[0]=0.f; s1[1]=0.f; s1[2]=0.f; s1[3]=0.f;
            mma16816(s0, qh, kh);     mma16816(s0, qh, kl);     mma16816(s0, ql, kh);
            mma16816(s1, qh, kh + 2); mma16816(s1, qh, kl + 2); mma16816(s1, ql, kh + 2);
        }

        // ---- exp (bound-shifted) ----
        #pragma unroll
        for (int j = 0; j < 8; j++) {
            S[j][0] = ex2f(fmaf(S[j][0], L2E, -bndA));
            S[j][1] = ex2f(fmaf(S[j][1], L2E, -bndA));
            S[j][2] = ex2f(fmaf(S[j][2], L2E, -bndB));
            S[j][3] = ex2f(fmaf(S[j][3], L2E, -bndB));
            sumA += S[j][0] + S[j][1];
            sumB += S[j][2] + S[j][3];
        }

        // ---- PV: O += ph*vh + pl*vh + ph*vl ----
        const uint32_t vhb = sb + SM_VH + bbuf*VBUF;
        const uint32_t vlb = sb + SM_VL + bbuf*VBUF;
        #pragma unroll
        for (int kt = 0; kt < 4; kt++) {
            const float* sa = S[2*kt];
            const float* sc = S[2*kt+1];
            uint32_t ph[4], pl[4];
            ph[0] = cvt2bf(sa[1], sa[0]);
            ph[1] = cvt2bf(sa[3], sa[2]);
            ph[2] = cvt2bf(sc[1], sc[0]);
            ph[3] = cvt2bf(sc[3], sc[2]);
            #pragma unroll
            for (int i = 0; i < 4; i++) {
                const float* s = (i < 2) ? sa : sc;
                int e = (i & 1)*2;
                float l0 = s[e]   - __uint_as_float(ph[i] << 16);
                float l1 = s[e+1] - __uint_as_float(ph[i] & 0xFFFF0000u);
                pl[i] = cvt2bf(l1, l0);
            }
            uint32_t rowoff = (kt*16 + (l & 7) + ((l >> 3) & 1)*8)*VSTRIDE + (l >> 4)*16;
            #pragma unroll
            for (int cp = 0; cp < 4; cp++) {
                uint32_t vh[4], vl[4];
                ldsm4t(vh, vhb + rowoff + cp*32);
                ldsm4t(vl, vlb + rowoff + cp*32);
                float* o0 = O[2*cp]; float* o1 = O[2*cp+1];
                mma16816(o0, ph, vh);     mma16816(o0, pl, vh);     mma16816(o0, ph, vl);
                mma16816(o1, ph, vh + 2); mma16816(o1, pl, vh + 2); mma16816(o1, ph, vl + 2);
            }
        }
        __syncthreads();
    }

    // ---- epilogue ----
    sumA += __shfl_xor_sync(0xffffffffu, sumA, 1);
    sumA += __shfl_xor_sync(0xffffffffu, sumA, 2);
    sumB += __shfl_xor_sync(0xffffffffu, sumB, 1);
    sumB += __shfl_xor_sync(0xffffffffu, sumB, 2);
    float invA = 1.0f / sumA;
    float invB = 1.0f / sumB;

    const int nA = n0 + qr0 + (l >> 2);
    #pragma unroll
    for (int j = 0; j < 8; j++) {
        int ch = j*8 + (l & 3)*2;
        float* base = out + (size_t)(b*CC + ch)*NN;
        base[nA]          = O[j][0] * invA;
        base[NN + nA]     = O[j][1] * invA;
        base[nA + 8]      = O[j][2] * invB;
        base[NN + nA + 8] = O[j][3] * invB;
    }
}

extern "C" void kernel_launch(void* const* d_in, const int* in_sizes, int n_in,
                              void* d_out, int out_size)
{
    const float* x  = (const float*)d_in[0];
    const float* Wq = (const float*)d_in[1];
    const float* bq = (const float*)d_in[2];
    const float* Wk = (const float*)d_in[3];
    const float* bk = (const float*)d_in[4];
    const float* Wv = (const float*)d_in[5];
    const float* bv = (const float*)d_in[6];
    float* out = (float*)d_out;

    cudaFuncSetAttribute(attn_kernel, cudaFuncAttributeMaxDynamicSharedMemorySize, SMEM_TOTAL);
    prep_kernel<<<BB*(NN/64), 64>>>(x, Wq, bq, Wk, bk, Wv, bv);
    attn_kernel<<<BB*(NN/MQ), 256, SMEM_TOTAL>>>(out);
}

// round 5
// speedup vs baseline: 8.2052x; 1.1061x over previous
#include <cuda_runtime.h>
#include <cuda_bf16.h>
#include <stdint.h>

#define BB 4
#define CC 64
#define WDIM 64
#define NN 4096
#define MQ 64
#define KTILE 32
#define NTILES (NN/KTILE)
#define L2E 1.44269504088896f

#define QSTRIDE 80
#define KSTRIDE 80
#define VSTRIDE 144
#define SM_Q   0
#define SM_K   5120
#define KBUF   2560
#define SM_VH  10240
#define VBUF   4608
#define SM_VL  19456
#define SMEM_TOTAL 28672

// ---- global scratch ----
__device__ float g_QPf[BB*NN*8];
__device__ int   g_maxk[BB][8];
__device__ __align__(16) __nv_bfloat16 g_Q16[BB*NN*32];
__device__ __align__(16) __nv_bfloat16 g_K16[BB*NN*32];
__device__ __align__(16) __nv_bfloat16 g_Vh[BB*NN*CC];
__device__ __align__(16) __nv_bfloat16 g_Vl[BB*NN*CC];

// ---- helpers ----
__device__ __forceinline__ uint32_t s2u(const void* p) {
    uint32_t a;
    asm("{ .reg .u64 t; cvta.to.shared.u64 t, %1; cvt.u32.u64 %0, t; }" : "=r"(a) : "l"(p));
    return a;
}
__device__ __forceinline__ float ex2f(float x) {
    float r; asm("ex2.approx.f32 %0, %1;" : "=f"(r) : "f"(x)); return r;
}
// packs: lower 16 bits = lo arg, upper 16 = hi arg
__device__ __forceinline__ uint32_t cvt2bf(float hi, float lo) {
    uint32_t r; asm("cvt.rn.bf16x2.f32 %0, %1, %2;" : "=r"(r) : "f"(hi), "f"(lo)); return r;
}
__device__ __forceinline__ void cpa16(uint32_t dst, const void* src) {
    asm volatile("cp.async.cg.shared.global [%0], [%1], 16;" :: "r"(dst), "l"(src));
}
__device__ __forceinline__ void ldsm4(uint32_t* r, uint32_t a) {
    asm volatile("ldmatrix.sync.aligned.m8n8.x4.shared.b16 {%0,%1,%2,%3}, [%4];"
        : "=r"(r[0]), "=r"(r[1]), "=r"(r[2]), "=r"(r[3]) : "r"(a));
}
__device__ __forceinline__ void ldsm4t(uint32_t* r, uint32_t a) {
    asm volatile("ldmatrix.sync.aligned.m8n8.x4.trans.shared.b16 {%0,%1,%2,%3}, [%4];"
        : "=r"(r[0]), "=r"(r[1]), "=r"(r[2]), "=r"(r[3]) : "r"(a));
}
__device__ __forceinline__ void mma16816(float* d, const uint32_t* a, const uint32_t* b) {
    asm volatile(
        "mma.sync.aligned.m16n8k16.row.col.f32.bf16.bf16.f32 "
        "{%0,%1,%2,%3}, {%4,%5,%6,%7}, {%8,%9}, {%0,%1,%2,%3};"
        : "+f"(d[0]), "+f"(d[1]), "+f"(d[2]), "+f"(d[3])
        : "r"(a[0]), "r"(a[1]), "r"(a[2]), "r"(a[3]), "r"(b[0]), "r"(b[1]));
}

// ---------------------------------------------------------------------------
// Prep: 1x1 convs -> packed bf16 operand tensors.  128 threads, 2 per pixel.
// Packed 32-dim score layout (per row):
//  Q: [0-7]=qh, [8]=qh0,[9]=qh1, [10-17]=qh, [18-25]=ql, [26]=ql0,[27]=ql1, [28-31]=0
//  K: [0-7]=kh, [8]=col,[9]=row, [10-17]=kl, [18-25]=kh, [26]=col,[27]=row, [28-31]=0
// ---------------------------------------------------------------------------
__global__ __launch_bounds__(128) void prep_kernel(
    const float* __restrict__ x,
    const float* __restrict__ Wq, const float* __restrict__ bq,
    const float* __restrict__ Wk, const float* __restrict__ bk,
    const float* __restrict__ Wv, const float* __restrict__ bv)
{
    __shared__ float xs[CC][64];
    __shared__ float wv_s[CC][CC];
    __shared__ float wq_s[8][CC];
    __shared__ float wk_s[8][CC];
    __shared__ float bv_s[CC];
    __shared__ float bq_s[8], bk_s[8];

    int b  = blockIdx.x >> 6;
    int n0 = (blockIdx.x & 63) * 64;
    int t  = threadIdx.x;

    for (int i = t; i < CC*64; i += 128)
        xs[i >> 6][i & 63] = x[(b*CC + (i >> 6))*NN + n0 + (i & 63)];
    for (int i = t; i < CC*CC; i += 128) wv_s[i/CC][i%CC] = Wv[i];
    for (int i = t; i < 8*CC;  i += 128) { wq_s[i/CC][i%CC] = Wq[i]; wk_s[i/CC][i%CC] = Wk[i]; }
    if (t < CC) bv_s[t] = bv[t];
    if (t < 8)  { bq_s[t] = bq[t]; bk_s[t] = bk[t]; }
    __syncthreads();

    const int h = t >> 6;        // warp-uniform
    const int p = t & 63;
    const int n = n0 + p;

    if (h == 0) {
        float accq[8], acck[8], accv[24];
        #pragma unroll
        for (int d = 0; d < 8; d++) { accq[d] = 0.f; acck[d] = 0.f; }
        #pragma unroll
        for (int e = 0; e < 24; e++) accv[e] = 0.f;
        for (int c = 0; c < CC; c++) {
            float xc = xs[c][p];
            #pragma unroll
            for (int d = 0; d < 8; d++) {
                accq[d] = fmaf(wq_s[d][c], xc, accq[d]);
                acck[d] = fmaf(wk_s[d][c], xc, acck[d]);
            }
            #pragma unroll
            for (int e = 0; e < 24; e++) accv[e] = fmaf(wv_s[e][c], xc, accv[e]);
        }

        float qv[8], kv[8];
        #pragma unroll
        for (int d = 0; d < 8; d++) { qv[d] = accq[d] + bq_s[d]; kv[d] = acck[d] + bk_s[d]; }
        #pragma unroll
        for (int d = 0; d < 8; d++) g_QPf[(size_t)(b*NN + n)*8 + d] = qv[d];

        #pragma unroll
        for (int d = 0; d < 8; d++) {
            float a = fabsf(kv[d]);
            #pragma unroll
            for (int o = 16; o > 0; o >>= 1)
                a = fmaxf(a, __shfl_xor_sync(0xffffffffu, a, o));
            if ((t & 31) == 0) atomicMax(&g_maxk[b][d], __float_as_int(a));
        }

        // ---- Q packed row ----
        {
            uint32_t u[16];
            float lo[8];
            #pragma unroll
            for (int i = 0; i < 4; i++) {
                uint32_t hh = cvt2bf(qv[2*i+1], qv[2*i]);
                u[i] = hh;
                lo[2*i]   = qv[2*i]   - __uint_as_float(hh << 16);
                lo[2*i+1] = qv[2*i+1] - __uint_as_float(hh & 0xFFFF0000u);
            }
            u[4] = u[0];
            u[5] = u[0]; u[6] = u[1]; u[7] = u[2]; u[8] = u[3];
            #pragma unroll
            for (int i = 0; i < 4; i++) u[9+i] = cvt2bf(lo[2*i+1], lo[2*i]);
            u[13] = u[9];
            u[14] = 0; u[15] = 0;
            uint4* dst = (uint4*)&g_Q16[(size_t)(b*NN + n)*32];
            dst[0] = make_uint4(u[0],u[1],u[2],u[3]);
            dst[1] = make_uint4(u[4],u[5],u[6],u[7]);
            dst[2] = make_uint4(u[8],u[9],u[10],u[11]);
            dst[3] = make_uint4(u[12],u[13],u[14],u[15]);
        }
        // ---- K packed row ----
        {
            uint32_t u[16];
            float lo[8];
            #pragma unroll
            for (int i = 0; i < 4; i++) {
                uint32_t hh = cvt2bf(kv[2*i+1], kv[2*i]);
                u[i] = hh;
                lo[2*i]   = kv[2*i]   - __uint_as_float(hh << 16);
                lo[2*i+1] = kv[2*i+1] - __uint_as_float(hh & 0xFFFF0000u);
            }
            float colc = (float)(n % WDIM) - 31.5f;   // exact in bf16
            float rowc = (float)(n / WDIM) - 31.5f;
            u[4] = cvt2bf(rowc, colc);
            #pragma unroll
            for (int i = 0; i < 4; i++) u[5+i] = cvt2bf(lo[2*i+1], lo[2*i]);
            u[9] = u[0]; u[10] = u[1]; u[11] = u[2]; u[12] = u[3];
            u[13] = u[4];
            u[14] = 0; u[15] = 0;
            uint4* dst = (uint4*)&g_K16[(size_t)(b*NN + n)*32];
            dst[0] = make_uint4(u[0],u[1],u[2],u[3]);
            dst[1] = make_uint4(u[4],u[5],u[6],u[7]);
            dst[2] = make_uint4(u[8],u[9],u[10],u[11]);
            dst[3] = make_uint4(u[12],u[13],u[14],u[15]);
        }
        // ---- V channels 0-23 ----
        #pragma unroll
        for (int e = 0; e < 24; e++) {
            float v = accv[e] + bv_s[e];
            __nv_bfloat16 vh = __float2bfloat16(v);
            g_Vh[(size_t)(b*NN + n)*CC + e] = vh;
            g_Vl[(size_t)(b*NN + n)*CC + e] = __float2bfloat16(v - __bfloat162float(vh));
        }
    } else {
        float accv[40];
        #pragma unroll
        for (int e = 0; e < 40; e++) accv[e] = 0.f;
        for (int c = 0; c < CC; c++) {
            float xc = xs[c][p];
            #pragma unroll
            for (int e = 0; e < 40; e++) accv[e] = fmaf(wv_s[24 + e][c], xc, accv[e]);
        }
        #pragma unroll
        for (int e = 0; e < 40; e++) {
            float v = accv[e] + bv_s[24 + e];
            __nv_bfloat16 vh = __float2bfloat16(v);
            g_Vh[(size_t)(b*NN + n)*CC + 24 + e] = vh;
            g_Vl[(size_t)(b*NN + n)*CC + 24 + e] = __float2bfloat16(v - __bfloat162float(vh));
        }
    }
}

// ---------------------------------------------------------------------------
// mma.sync flash attention: 256 CTAs x 128 threads (4 warps x 16 query rows),
// 64 queries/CTA, 32-key tiles, packed 32-dim score contraction,
// bound-based softmax (no row max, no rescale).
// ---------------------------------------------------------------------------
#define STAGE(tile, bbuf) do {                                              \
    int m0s = (tile)*KTILE;                                                 \
    { int row = t >> 2, seg = t & 3;                                        \
      cpa16(sb + SM_K + (bbuf)*KBUF + row*KSTRIDE + seg*16,                 \
            &g_K16[(size_t)(b*NN + m0s + row)*32 + seg*8]); }               \
    _Pragma("unroll")                                                       \
    for (int j5 = 0; j5 < 2; j5++) {                                        \
        int id = t + 128*j5; int row = id >> 3, seg = id & 7;               \
        cpa16(sb + SM_VH + (bbuf)*VBUF + row*VSTRIDE + seg*16,              \
              &g_Vh[(size_t)(b*NN + m0s + row)*CC + seg*8]);                \
        cpa16(sb + SM_VL + (bbuf)*VBUF + row*VSTRIDE + seg*16,              \
              &g_Vl[(size_t)(b*NN + m0s + row)*CC + seg*8]);                \
    }                                                                       \
} while (0)

__global__ __launch_bounds__(128, 2) void attn_kernel(float* __restrict__ out)
{
    extern __shared__ char smem[];
    const uint32_t sb = s2u(smem);
    const int t = threadIdx.x;
    const int w = t >> 5;
    const int l = t & 31;
    const int b  = blockIdx.x >> 6;
    const int n0 = (blockIdx.x & 63) * MQ;
    const int qr0 = w * 16;

    // stage Q (plain loads): 64 rows x 64B
    #pragma unroll
    for (int j = 0; j < 2; j++) {
        int id = t + 128*j;
        int row = id >> 2, seg = id & 3;
        uint4 v = *(const uint4*)&g_Q16[(size_t)(b*NN + n0 + row)*32 + seg*8];
        *(uint4*)(smem + SM_Q + row*QSTRIDE + seg*16) = v;
    }

    // prefetch tile 0
    STAGE(0, 0);
    asm volatile("cp.async.commit_group;" ::: "memory");

    // softmax bounds for this lane's two query rows
    float bndA, bndB;
    {
        int rA = n0 + qr0 + (l >> 2);
        const float* qa = &g_QPf[(size_t)(b*NN + rA)*8];
        const float* qb = qa + 8*8;
        float ba = 0.f, bb2 = 0.f;
        #pragma unroll
        for (int d = 0; d < 8; d++) {
            float mk = __int_as_float(g_maxk[b][d]);
            float qda = fabsf(qa[d]), qdb = fabsf(qb[d]);
            ba  = fmaf(qda, mk, ba);
            bb2 = fmaf(qdb, mk, bb2);
            if (d < 2) { ba += 31.5f*qda; bb2 += 31.5f*qdb; }
        }
        bndA = ba * L2E; bndB = bb2 * L2E;
    }

    __syncthreads();   // Q staged

    uint32_t qA[4], qB[4];
    {
        uint32_t qa = sb + SM_Q + (qr0 + (l & 7) + ((l >> 3) & 1)*8)*QSTRIDE + (l >> 4)*16;
        ldsm4(qA, qa);
        ldsm4(qB, qa + 32);
    }

    float O[8][4];
    #pragma unroll
    for (int j = 0; j < 8; j++) { O[j][0]=0.f; O[j][1]=0.f; O[j][2]=0.f; O[j][3]=0.f; }
    float sumA = 0.f, sumB = 0.f;

    for (int tt = 0; tt < NTILES; tt++) {
        const int bbuf = tt & 1;
        if (tt + 1 < NTILES) STAGE(tt + 1, (tt + 1) & 1);
        asm volatile("cp.async.commit_group;" ::: "memory");
        asm volatile("cp.async.wait_group 1;" ::: "memory");
        __syncthreads();

        // ---- scores: single packed 32-dim contraction ----
        const uint32_t kbase = sb + SM_K + bbuf*KBUF;
        float S[4][4];
        #pragma unroll
        for (int p2 = 0; p2 < 2; p2++) {
            uint32_t ka = kbase + (p2*16 + (l & 7) + (l >> 4)*8)*KSTRIDE + ((l >> 3) & 1)*16;
            uint32_t kA[4], kB[4];
            ldsm4(kA, ka);
            ldsm4(kB, ka + 32);
            float* s0 = S[2*p2]; float* s1 = S[2*p2+1];
            s0[0]=0.f; s0[1]=0.f; s0[2]=0.f; s0[3]=0.f;
            s1[0]=0.f; s1[1]=0.f; s1[2]=0.f; s1[3]=0.f;
            mma16816(s0, qA, kA);     mma16816(s0, qB, kB);
            mma16816(s1, qA, kA + 2); mma16816(s1, qB, kB + 2);
        }

        // ---- exp (bound-shifted, no row max) ----
        #pragma unroll
        for (int j = 0; j < 4; j++) {
            S[j][0] = ex2f(fmaf(S[j][0], L2E, -bndA));
            S[j][1] = ex2f(fmaf(S[j][1], L2E, -bndA));
            S[j][2] = ex2f(fmaf(S[j][2], L2E, -bndB));
            S[j][3] = ex2f(fmaf(S[j][3], L2E, -bndB));
            sumA += S[j][0] + S[j][1];
            sumB += S[j][2] + S[j][3];
        }

        // ---- PV: O += ph*vh + pl*vh + ph*vl ----
        const uint32_t vhb = sb + SM_VH + bbuf*VBUF;
        const uint32_t vlb = sb + SM_VL + bbuf*VBUF;
        #pragma unroll
        for (int kt = 0; kt < 2; kt++) {
            const float* sa = S[2*kt];
            const float* sc = S[2*kt+1];
            uint32_t ph[4], pl[4];
            ph[0] = cvt2bf(sa[1], sa[0]);
            ph[1] = cvt2bf(sa[3], sa[2]);
            ph[2] = cvt2bf(sc[1], sc[0]);
            ph[3] = cvt2bf(sc[3], sc[2]);
            #pragma unroll
            for (int i = 0; i < 4; i++) {
                const float* s = (i < 2) ? sa : sc;
                int e = (i & 1)*2;
                float l0 = s[e]   - __uint_as_float(ph[i] << 16);
                float l1 = s[e+1] - __uint_as_float(ph[i] & 0xFFFF0000u);
                pl[i] = cvt2bf(l1, l0);
            }
            uint32_t rowoff = (kt*16 + (l & 7) + ((l >> 3) & 1)*8)*VSTRIDE + (l >> 4)*16;
            #pragma unroll
            for (int cp = 0; cp < 4; cp++) {
                uint32_t vh[4], vl[4];
                ldsm4t(vh, vhb + rowoff + cp*32);
                ldsm4t(vl, vlb + rowoff + cp*32);
                float* o0 = O[2*cp]; float* o1 = O[2*cp+1];
                mma16816(o0, ph, vh);     mma16816(o0, pl, vh);     mma16816(o0, ph, vl);
                mma16816(o1, ph, vh + 2); mma16816(o1, pl, vh + 2); mma16816(o1, ph, vl + 2);
            }
        }
        __syncthreads();
    }

    // ---- epilogue ----
    sumA += __shfl_xor_sync(0xffffffffu, sumA, 1);
    sumA += __shfl_xor_sync(0xffffffffu, sumA, 2);
    sumB += __shfl_xor_sync(0xffffffffu, sumB, 1);
    sumB += __shfl_xor_sync(0xffffffffu, sumB, 2);
    float invA = 1.0f / sumA;
    float invB = 1.0f / sumB;

    const int nA = n0 + qr0 + (l >> 2);
    #pragma unroll
    for (int j = 0; j < 8; j++) {
        int ch = j*8 + (l & 3)*2;
        float* base = out + (size_t)(b*CC + ch)*NN;
        base[nA]          = O[j][0] * invA;
        base[NN + nA]     = O[j][1] * invA;
        base[nA + 8]      = O[j][2] * invB;
        base[NN + nA + 8] = O[j][3] * invB;
    }
}

extern "C" void kernel_launch(void* const* d_in, const int* in_sizes, int n_in,
                              void* d_out, int out_size)
{
    const float* x  = (const float*)d_in[0];
    const float* Wq = (const float*)d_in[1];
    const float* bq = (const float*)d_in[2];
    const float* Wk = (const float*)d_in[3];
    const float* bk = (const float*)d_in[4];
    const float* Wv = (const float*)d_in[5];
    const float* bv = (const float*)d_in[6];
    float* out = (float*)d_out;

    prep_kernel<<<BB*(NN/64), 128>>>(x, Wq, bq, Wk, bk, Wv, bv);
    attn_kernel<<<BB*(NN/MQ), 128, SMEM_TOTAL>>>(out);
}